// round 3
// baseline (speedup 1.0000x reference)
#include <cuda_runtime.h>
#include <cstdint>

#define BATCH 4
#define NPTS  4096
#define NSAMP 1024
#define KNB   32
#define NCENT 4096          // BATCH*NSAMP
#define NPCOL 131072        // NCENT*KNB

// ---------------- scratch (static device memory: allowed) ----------------
__device__ int   g_cent[NCENT];
__device__ int   g_knn[NCENT * KNB];
__device__ float g_w12[256 * 6];
__device__ float g_h2[(size_t)256 * NPCOL];   // 128 MB (conv2 pre-act; reused as conv4 output)
__device__ float g_xm[256 * NCENT];           // 4 MB
__device__ float g_c1[(size_t)512 * NCENT];   // 8 MB  (w3[:, :256] @ xm)
__device__ float g_h3[(size_t)512 * NPCOL];   // 256 MB
__device__ float g_sum[512], g_sq[512];
__device__ float g_s2[256], g_t2[256];
__device__ float g_s3[512], g_t3[512];
__device__ float g_s4[256], g_t4[256];

// ---------------- helpers ----------------
__device__ __forceinline__ unsigned fkey(float x) {
    unsigned u = __float_as_uint(x);
    u ^= (u & 0x80000000u) ? 0xFFFFFFFFu : 0x80000000u;
    return u;
}

// packed fp32 FMA (sm_100+): d = a*b + d, lane-wise on 2 floats
__device__ __forceinline__ void ffma2(unsigned long long& d,
                                      unsigned long long a, unsigned long long b) {
    asm("fma.rn.f32x2 %0, %1, %2, %0;" : "+l"(d) : "l"(a), "l"(b));
}
__device__ __forceinline__ void unpack2(float& lo, float& hi, unsigned long long v) {
    asm("mov.b64 {%0, %1}, %2;" : "=f"(lo), "=f"(hi) : "l"(v));
}

// ---------------- FPS: one block per batch, sequential argmax ----------------
__global__ void fps_kernel(const float* __restrict__ p, float* __restrict__ out)
{
    extern __shared__ float sm[];
    float* sx = sm;
    float* sy = sm + NPTS;
    float* sz = sm + 2 * NPTS;
    __shared__ unsigned long long wmax[32];
    __shared__ float cc[3];

    int b = blockIdx.x, t = threadIdx.x;
    const float* pb = p + (size_t)b * NPTS * 3;
    for (int i = t; i < NPTS; i += 1024) {
        sx[i] = pb[3 * i]; sy[i] = pb[3 * i + 1]; sz[i] = pb[3 * i + 2];
    }
    float dmin[4];
#pragma unroll
    for (int j = 0; j < 4; j++) dmin[j] = 1e10f;
    __syncthreads();
    if (t == 0) {
        g_cent[b * NSAMP] = 0;
        out[(size_t)(b * NSAMP) * 3 + 0] = sx[0];
        out[(size_t)(b * NSAMP) * 3 + 1] = sy[0];
        out[(size_t)(b * NSAMP) * 3 + 2] = sz[0];
        cc[0] = sx[0]; cc[1] = sy[0]; cc[2] = sz[0];
    }
    __syncthreads();

    int lane = t & 31, warp = t >> 5;
    for (int it = 1; it < NSAMP; it++) {
        float cx = cc[0], cy = cc[1], cz = cc[2];
        unsigned long long best = 0ull;
#pragma unroll
        for (int j = 0; j < 4; j++) {
            int i = t + j * 1024;
            float dx = __fsub_rn(sx[i], cx);
            float dy = __fsub_rn(sy[i], cy);
            float dz = __fsub_rn(sz[i], cz);
            float d = __fadd_rn(__fadd_rn(__fmul_rn(dx, dx), __fmul_rn(dy, dy)), __fmul_rn(dz, dz));
            dmin[j] = fminf(dmin[j], d);
            unsigned long long key =
                ((unsigned long long)__float_as_uint(dmin[j]) << 32) | (unsigned)(~i);
            best = key > best ? key : best;
        }
#pragma unroll
        for (int o = 16; o; o >>= 1) {
            unsigned long long v = __shfl_xor_sync(0xFFFFFFFFu, best, o);
            best = v > best ? v : best;
        }
        if (lane == 0) wmax[warp] = best;
        __syncthreads();
        if (warp == 0) {
            best = wmax[lane];
#pragma unroll
            for (int o = 16; o; o >>= 1) {
                unsigned long long v = __shfl_xor_sync(0xFFFFFFFFu, best, o);
                best = v > best ? v : best;
            }
            if (lane == 0) {
                int idx = (int)(~(unsigned)(best & 0xFFFFFFFFull));
                g_cent[b * NSAMP + it] = idx;
                size_t o3 = (size_t)(b * NSAMP + it) * 3;
                out[o3 + 0] = sx[idx]; out[o3 + 1] = sy[idx]; out[o3 + 2] = sz[idx];
                cc[0] = sx[idx]; cc[1] = sy[idx]; cc[2] = sz[idx];
            }
        }
        __syncthreads();
    }
}

// ---------------- KNN ----------------
__global__ void knn_kernel(const float* __restrict__ p)
{
    extern __shared__ float sm[];
    float* sx = sm;
    float* sy = sm + NPTS;
    float* sz = sm + 2 * NPTS;

    int b = blockIdx.x >> 5;
    int blk = blockIdx.x & 31;
    const float* pb = p + (size_t)b * NPTS * 3;
    int t = threadIdx.x;
    for (int i = t; i < NPTS; i += 256) {
        sx[i] = pb[3 * i]; sy[i] = pb[3 * i + 1]; sz[i] = pb[3 * i + 2];
    }
    __syncthreads();
    int warp = t >> 5, lane = t & 31;

    for (int q = 0; q < 4; q++) {
        int sc = (blk * 8 + warp) * 4 + q;
        int ci = g_cent[b * NSAMP + sc];
        float cx = sx[ci], cy = sy[ci], cz = sz[ci];
        float normc = __fadd_rn(__fadd_rn(__fmul_rn(cx, cx), __fmul_rn(cy, cy)), __fmul_rn(cz, cz));

        auto makekey = [&](int j) -> unsigned long long {
            float px = sx[j], py = sy[j], pz = sz[j];
            float normp = __fadd_rn(__fadd_rn(__fmul_rn(px, px), __fmul_rn(py, py)), __fmul_rn(pz, pz));
            float dot = __fadd_rn(__fadd_rn(__fmul_rn(cx, px), __fmul_rn(cy, py)), __fmul_rn(cz, pz));
            float d2 = __fsub_rn(__fadd_rn(normc, normp), __fmul_rn(2.0f, dot));
            return ((unsigned long long)fkey(d2) << 32) | (unsigned)j;
        };

        unsigned long long best = makekey(lane);
        unsigned long long thresh;
        {
            unsigned long long mv = best;
#pragma unroll
            for (int o = 16; o; o >>= 1) {
                unsigned long long v = __shfl_xor_sync(0xFFFFFFFFu, mv, o);
                mv = v > mv ? v : mv;
            }
            thresh = mv;
        }
        for (int chunk = 1; chunk < NPTS / 32; chunk++) {
            unsigned long long cand = makekey(chunk * 32 + lane);
            unsigned mask = __ballot_sync(0xFFFFFFFFu, cand < thresh);
            while (mask) {
                int src = __ffs(mask) - 1;
                mask &= mask - 1;
                unsigned long long v = __shfl_sync(0xFFFFFFFFu, cand, src);
                unsigned long long mv = best; int ml = lane;
#pragma unroll
                for (int o = 16; o; o >>= 1) {
                    unsigned long long ov = __shfl_xor_sync(0xFFFFFFFFu, mv, o);
                    int ol = __shfl_xor_sync(0xFFFFFFFFu, ml, o);
                    if (ov > mv) { mv = ov; ml = ol; }
                }
                if (v < mv && lane == ml) best = v;
                thresh = mv;
            }
        }
        g_knn[(size_t)(b * NSAMP + sc) * KNB + lane] = (int)(unsigned)(best & 0xFFFFFFFFull);
    }
}

// ---------------- w12 = w2 @ w1 (256x6) ----------------
__global__ void w12_kernel(const float* __restrict__ w1, const float* __restrict__ w2)
{
    int o = threadIdx.x;
    float acc[6] = {0, 0, 0, 0, 0, 0};
    for (int m = 0; m < 256; m++) {
        float wm = w2[o * 256 + m];
#pragma unroll
        for (int j = 0; j < 6; j++) acc[j] = fmaf(wm, w1[m * 6 + j], acc[j]);
    }
#pragma unroll
    for (int j = 0; j < 6; j++) g_w12[o * 6 + j] = acc[j];
}

// ---------------- stage1: gather + fused conv1+conv2 -> h2 ----------------
__global__ void stage1_kernel(const float* __restrict__ p, const float* __restrict__ f,
                              const float* __restrict__ b2)
{
    __shared__ float x0s[6][KNB];
    __shared__ float ws[256 * 6 + 256];
    int pt = blockIdx.x;
    int b = pt >> 10;
    int t = threadIdx.x;
    for (int i = t; i < 256 * 6 + 256; i += 256)
        ws[i] = (i < 1536) ? g_w12[i] : b2[i - 1536];
    if (t < KNB) {
        int idx = g_knn[(size_t)pt * KNB + t];
        const float* pp = p + (size_t)(b * NPTS + idx) * 3;
        x0s[0][t] = pp[0]; x0s[1][t] = pp[1]; x0s[2][t] = pp[2];
        x0s[3][t] = f[(size_t)(b * 3 + 0) * NPTS + idx];
        x0s[4][t] = f[(size_t)(b * 3 + 1) * NPTS + idx];
        x0s[5][t] = f[(size_t)(b * 3 + 2) * NPTS + idx];
    }
    __syncthreads();
    int k = t & 31, cg = t >> 5;
    float v0 = x0s[0][k], v1 = x0s[1][k], v2 = x0s[2][k],
          v3 = x0s[3][k], v4 = x0s[4][k], v5 = x0s[5][k];
#pragma unroll 4
    for (int m = 0; m < 32; m++) {
        int c = cg * 32 + m;
        float acc = ws[1536 + c];
        acc = fmaf(ws[c * 6 + 0], v0, acc);
        acc = fmaf(ws[c * 6 + 1], v1, acc);
        acc = fmaf(ws[c * 6 + 2], v2, acc);
        acc = fmaf(ws[c * 6 + 3], v3, acc);
        acc = fmaf(ws[c * 6 + 4], v4, acc);
        acc = fmaf(ws[c * 6 + 5], v5, acc);
        g_h2[(size_t)c * NPCOL + (size_t)pt * KNB + k] = acc;
    }
}

// ---------------- BN stats: one block per channel ----------------
__global__ void bnstats_kernel(int which)
{
    const float* src = (which == 1) ? g_h3 : g_h2;
    int c = blockIdx.x;
    int t = threadIdx.x;
    const float4* row = (const float4*)(src + (size_t)c * NPCOL);
    float s = 0.f, q = 0.f;
    for (int i = t; i < NPCOL / 4; i += 256) {
        float4 v = row[i];
        s += v.x + v.y + v.z + v.w;
        q += v.x * v.x + v.y * v.y + v.z * v.z + v.w * v.w;
    }
    __shared__ float rs[256], rq[256];
    rs[t] = s; rq[t] = q;
    __syncthreads();
    for (int o = 128; o; o >>= 1) {
        if (t < o) { rs[t] += rs[t + o]; rq[t] += rq[t + o]; }
        __syncthreads();
    }
    if (t == 0) { g_sum[c] = rs[0]; g_sq[c] = rq[0]; }
}

__global__ void bnfinal_kernel(int which, int n, const float* __restrict__ g,
                               const float* __restrict__ be)
{
    int c = blockIdx.x * blockDim.x + threadIdx.x;
    if (c >= n) return;
    float inv = 1.0f / (float)NPCOL;
    float mean = g_sum[c] * inv;
    float var  = g_sq[c] * inv - mean * mean;
    float s = g[c] * rsqrtf(var + 1e-5f);
    float tt = be[c] - mean * s;
    if (which == 0) { g_s2[c] = s; g_t2[c] = tt; }
    else if (which == 1) { g_s3[c] = s; g_t3[c] = tt; }
    else { g_s4[c] = s; g_t4[c] = tt; }
}

// ---------------- xm = max_k relu(bn2(h2)) ----------------
__global__ void xm_kernel()
{
    int gid = blockIdx.x * 256 + threadIdx.x;
    int c = gid >> 12, pt = gid & 4095;
    float s = g_s2[c], t = g_t2[c];
    const float4* src = (const float4*)(g_h2 + (size_t)c * NPCOL + (size_t)pt * KNB);
    float m = 0.f;
#pragma unroll
    for (int i = 0; i < 8; i++) {
        float4 v = src[i];
        m = fmaxf(m, fmaxf(fmaxf(fmaf(v.x, s, t), fmaf(v.y, s, t)),
                           fmaxf(fmaf(v.z, s, t), fmaf(v.w, s, t))));
    }
    g_xm[c * NCENT + pt] = m;
}

// ---------------- C1(512 x 4096) = w3[:, 0:256] @ xm(256 x 4096) ----------------
__global__ __launch_bounds__(256, 2) void c1_kernel(const float* __restrict__ w3)
{
    __shared__ __align__(16) float As[16][128];
    __shared__ __align__(16) float Bs[16][128];
    int n0 = blockIdx.x * 128, m0 = blockIdx.y * 128;
    int tid = threadIdx.x, tx = tid & 15, ty = tid >> 4;
    float acc[8][8];
#pragma unroll
    for (int i = 0; i < 8; i++)
#pragma unroll
        for (int j = 0; j < 8; j++) acc[i][j] = 0.f;

    for (int k0 = 0; k0 < 256; k0 += 16) {
        {
            int m = tid >> 1, kq = (tid & 1) * 8;
            const float4* ap = (const float4*)(w3 + (size_t)(m0 + m) * 512 + k0 + kq);
            float4 a0 = ap[0], a1 = ap[1];
            As[kq + 0][m] = a0.x; As[kq + 1][m] = a0.y; As[kq + 2][m] = a0.z; As[kq + 3][m] = a0.w;
            As[kq + 4][m] = a1.x; As[kq + 5][m] = a1.y; As[kq + 6][m] = a1.z; As[kq + 7][m] = a1.w;
        }
        {
            int r = tid >> 4, c8 = (tid & 15) * 8;
            const float4* bp = (const float4*)(g_xm + (size_t)(k0 + r) * NCENT + n0 + c8);
            float4 b0 = bp[0], b1 = bp[1];
            *(float4*)&Bs[r][c8] = b0;
            *(float4*)&Bs[r][c8 + 4] = b1;
        }
        __syncthreads();
#pragma unroll
        for (int kk = 0; kk < 16; kk++) {
            float a[8], bb[8];
            *(float4*)(&a[0]) = *(const float4*)(&As[kk][ty * 8]);
            *(float4*)(&a[4]) = *(const float4*)(&As[kk][ty * 8 + 4]);
            *(float4*)(&bb[0]) = *(const float4*)(&Bs[kk][tx * 8]);
            *(float4*)(&bb[4]) = *(const float4*)(&Bs[kk][tx * 8 + 4]);
#pragma unroll
            for (int i = 0; i < 8; i++)
#pragma unroll
                for (int j = 0; j < 8; j++)
                    acc[i][j] = fmaf(a[i], bb[j], acc[i][j]);
        }
        __syncthreads();
    }
#pragma unroll
    for (int i = 0; i < 8; i++) {
        float* cp = g_c1 + (size_t)(m0 + ty * 8 + i) * NCENT + n0 + tx * 8;
        *(float4*)cp = make_float4(acc[i][0], acc[i][1], acc[i][2], acc[i][3]);
        *(float4*)(cp + 4) = make_float4(acc[i][4], acc[i][5], acc[i][6], acc[i][7]);
    }
}

// ---------------- main GEMM with packed f32x2 FMA ----------------
// mode 0: g_h3(512 x NPCOL) = w3[:,256:512] @ relu(bn2(h2))  + C1[:, n>>5]
// mode 1: g_h2(256 x NPCOL) = w4 @ relu(bn3(h3))
#define BM 128
#define BNN 128
#define BK 16
__global__ __launch_bounds__(256, 2) void gemm_kernel(int mode, const float* __restrict__ W)
{
    __shared__ __align__(16) float2 As2[BK][BM];     // duplicated A: {a,a}
    __shared__ __align__(16) float  Bs[BK][BNN];
    int n0 = blockIdx.x * BNN;
    int m0 = blockIdx.y * BM;
    int tid = threadIdx.x;
    int tx = tid & 15, ty = tid >> 4;

    const int   KD   = (mode == 0) ? 256 : 512;
    const int   kofs = (mode == 0) ? 256 : 0;        // w3 cols 256.. for the h2 part
    const float* Hsrc = (mode == 0) ? g_h2 : g_h3;
    const float* Sarr = (mode == 0) ? g_s2 : g_s3;
    const float* Tarr = (mode == 0) ? g_t2 : g_t3;

    unsigned long long acc2[8][4];
#pragma unroll
    for (int i = 0; i < 8; i++)
#pragma unroll
        for (int j = 0; j < 4; j++) acc2[i][j] = 0ull;

    for (int k0 = 0; k0 < KD; k0 += BK) {
        // A tile: duplicated pairs
        {
            int m = tid >> 1, kq = (tid & 1) * 8;
            const float4* ap = (const float4*)(W + (size_t)(m0 + m) * 512 + kofs + k0 + kq);
            float4 a0 = ap[0], a1 = ap[1];
            As2[kq + 0][m] = make_float2(a0.x, a0.x);
            As2[kq + 1][m] = make_float2(a0.y, a0.y);
            As2[kq + 2][m] = make_float2(a0.z, a0.z);
            As2[kq + 3][m] = make_float2(a0.w, a0.w);
            As2[kq + 4][m] = make_float2(a1.x, a1.x);
            As2[kq + 5][m] = make_float2(a1.y, a1.y);
            As2[kq + 6][m] = make_float2(a1.z, a1.z);
            As2[kq + 7][m] = make_float2(a1.w, a1.w);
        }
        // B tile: relu(bn(h)) on the fly
        {
            int r = tid >> 4, c8 = (tid & 15) * 8;
            int i = k0 + r;
            float s = Sarr[i], tt = Tarr[i];
            const float4* hp = (const float4*)(Hsrc + (size_t)i * NPCOL + n0 + c8);
            float4 h0 = hp[0], h1 = hp[1];
            Bs[r][c8 + 0] = fmaxf(fmaf(h0.x, s, tt), 0.f);
            Bs[r][c8 + 1] = fmaxf(fmaf(h0.y, s, tt), 0.f);
            Bs[r][c8 + 2] = fmaxf(fmaf(h0.z, s, tt), 0.f);
            Bs[r][c8 + 3] = fmaxf(fmaf(h0.w, s, tt), 0.f);
            Bs[r][c8 + 4] = fmaxf(fmaf(h1.x, s, tt), 0.f);
            Bs[r][c8 + 5] = fmaxf(fmaf(h1.y, s, tt), 0.f);
            Bs[r][c8 + 6] = fmaxf(fmaf(h1.z, s, tt), 0.f);
            Bs[r][c8 + 7] = fmaxf(fmaf(h1.w, s, tt), 0.f);
        }
        __syncthreads();
#pragma unroll
        for (int kk = 0; kk < BK; kk++) {
            const unsigned long long* ap2 = (const unsigned long long*)&As2[kk][ty * 8];
            const unsigned long long* bp2 = (const unsigned long long*)&Bs[kk][tx * 8];
            unsigned long long av[8], bv[4];
#pragma unroll
            for (int i = 0; i < 8; i++) av[i] = ap2[i];
#pragma unroll
            for (int j = 0; j < 4; j++) bv[j] = bp2[j];
#pragma unroll
            for (int i = 0; i < 8; i++)
#pragma unroll
                for (int j = 0; j < 4; j++)
                    ffma2(acc2[i][j], av[i], bv[j]);
        }
        __syncthreads();
    }

    // epilogue
    float c1v[8];
    if (mode == 0) {
        int pt = (n0 + tx * 8) >> 5;                 // 8 cols share one point
#pragma unroll
        for (int i = 0; i < 8; i++)
            c1v[i] = g_c1[(size_t)(m0 + ty * 8 + i) * NCENT + pt];
    } else {
#pragma unroll
        for (int i = 0; i < 8; i++) c1v[i] = 0.f;
    }
    float* C = (mode == 0) ? g_h3 : g_h2;
#pragma unroll
    for (int i = 0; i < 8; i++) {
        float o[8];
#pragma unroll
        for (int j = 0; j < 4; j++) {
            float lo, hi;
            unpack2(lo, hi, acc2[i][j]);
            o[2 * j]     = lo + c1v[i];
            o[2 * j + 1] = hi + c1v[i];
        }
        float* cp = C + (size_t)(m0 + ty * 8 + i) * NPCOL + n0 + tx * 8;
        *(float4*)cp       = make_float4(o[0], o[1], o[2], o[3]);
        *(float4*)(cp + 4) = make_float4(o[4], o[5], o[6], o[7]);
    }
}

// ---------------- final: out_feat = max_k relu(bn4(h4)) ----------------
__global__ void final_kernel(float* __restrict__ out)
{
    int gid = blockIdx.x * 256 + threadIdx.x;
    int c = gid >> 12, pt = gid & 4095;
    float s = g_s4[c], t = g_t4[c];
    const float4* src = (const float4*)(g_h2 + (size_t)c * NPCOL + (size_t)pt * KNB);
    float m = 0.f;
#pragma unroll
    for (int i = 0; i < 8; i++) {
        float4 v = src[i];
        m = fmaxf(m, fmaxf(fmaxf(fmaf(v.x, s, t), fmaf(v.y, s, t)),
                           fmaxf(fmaf(v.z, s, t), fmaf(v.w, s, t))));
    }
    int b = pt >> 10, sIdx = pt & 1023;
    out[12288 + (size_t)((b << 8) + c) * 1024 + sIdx] = m;
}

// ---------------- launch ----------------
extern "C" void kernel_launch(void* const* d_in, const int* in_sizes, int n_in,
                              void* d_out, int out_size)
{
    const float* p   = (const float*)d_in[0];
    const float* f   = (const float*)d_in[1];
    const float* w1  = (const float*)d_in[2];
    const float* w2  = (const float*)d_in[3];
    const float* b2  = (const float*)d_in[4];
    const float* g2  = (const float*)d_in[5];
    const float* be2 = (const float*)d_in[6];
    const float* w3  = (const float*)d_in[7];
    const float* g3  = (const float*)d_in[8];
    const float* be3 = (const float*)d_in[9];
    const float* w4  = (const float*)d_in[10];
    const float* g4  = (const float*)d_in[11];
    const float* be4 = (const float*)d_in[12];
    float* out = (float*)d_out;

    cudaFuncSetAttribute(fps_kernel, cudaFuncAttributeMaxDynamicSharedMemorySize, 65536);
    cudaFuncSetAttribute(knn_kernel, cudaFuncAttributeMaxDynamicSharedMemorySize, 65536);

    w12_kernel<<<1, 256>>>(w1, w2);
    fps_kernel<<<BATCH, 1024, NPTS * 3 * sizeof(float)>>>(p, out);
    knn_kernel<<<BATCH * 32, 256, NPTS * 3 * sizeof(float)>>>(p);
    stage1_kernel<<<NCENT, 256>>>(p, f, b2);

    bnstats_kernel<<<256, 256>>>(0);
    bnfinal_kernel<<<1, 256>>>(0, 256, g2, be2);
    xm_kernel<<<NCENT, 256>>>();
    c1_kernel<<<dim3(NCENT / 128, 512 / 128), 256>>>(w3);

    gemm_kernel<<<dim3(NPCOL / BNN, 512 / BM), 256>>>(0, w3);
    bnstats_kernel<<<512, 256>>>(1);
    bnfinal_kernel<<<2, 256>>>(1, 512, g3, be3);

    gemm_kernel<<<dim3(NPCOL / BNN, 256 / BM), 256>>>(1, w4);
    bnstats_kernel<<<256, 256>>>(2);
    bnfinal_kernel<<<1, 256>>>(2, 256, g4, be4);

    final_kernel<<<NCENT, 256>>>(out);
}

// round 5
// speedup vs baseline: 2.6288x; 2.6288x over previous
#include <cuda_runtime.h>
#include <cuda_bf16.h>
#include <cstdint>

#define BATCH 4
#define NPTS  4096
#define NSAMP 1024
#define KNB   32
#define NCENT 4096          // BATCH*NSAMP
#define NPCOL 131072        // NCENT*KNB

// ---------------- scratch (static device memory: keep total < ~400MB) ----------------
__device__ int   g_cent[NCENT];
__device__ int   g_knn[NCENT * KNB];
__device__ float g_w12[256 * 6];
__device__ float g_h2[(size_t)256 * NPCOL];   // 128 MB: h2 fp32 -> in-place split2 -> h4 fp32
__device__ float g_xm[256 * NCENT];           // 4 MB
__device__ float g_c1[(size_t)512 * NCENT];   // 8 MB  (w3[:, :256] @ xm)
__device__ float g_h3[(size_t)512 * NPCOL];   // 256 MB: h3 fp32 -> in-place split3
__device__ __nv_bfloat16 g_wh3[512 * 256], g_wl3[512 * 256];
__device__ __nv_bfloat16 g_wh4[256 * 512], g_wl4[256 * 512];
__device__ float g_sum[512], g_sq[512];
__device__ float g_s2[256], g_t2[256];
__device__ float g_s3[512], g_t3[512];
__device__ float g_s4[256], g_t4[256];

// ---------------- helpers ----------------
__device__ __forceinline__ unsigned fkey(float x) {
    unsigned u = __float_as_uint(x);
    u ^= (u & 0x80000000u) ? 0xFFFFFFFFu : 0x80000000u;
    return u;
}
__device__ __forceinline__ unsigned sm_u32(const void* p) {
    return (unsigned)__cvta_generic_to_shared(p);
}
__device__ __forceinline__ void ldsm4(unsigned r[4], unsigned addr) {
    asm volatile("ldmatrix.sync.aligned.m8n8.x4.shared.b16 {%0,%1,%2,%3}, [%4];"
                 : "=r"(r[0]), "=r"(r[1]), "=r"(r[2]), "=r"(r[3]) : "r"(addr));
}
__device__ __forceinline__ void ldsm4t(unsigned r[4], unsigned addr) {
    asm volatile("ldmatrix.sync.aligned.m8n8.x4.trans.shared.b16 {%0,%1,%2,%3}, [%4];"
                 : "=r"(r[0]), "=r"(r[1]), "=r"(r[2]), "=r"(r[3]) : "r"(addr));
}
__device__ __forceinline__ void mma16816(float d[4], const unsigned a[4], const unsigned b[2]) {
    asm volatile("mma.sync.aligned.m16n8k16.row.col.f32.bf16.bf16.f32 "
                 "{%0,%1,%2,%3}, {%4,%5,%6,%7}, {%8,%9}, {%0,%1,%2,%3};"
                 : "+f"(d[0]), "+f"(d[1]), "+f"(d[2]), "+f"(d[3])
                 : "r"(a[0]), "r"(a[1]), "r"(a[2]), "r"(a[3]), "r"(b[0]), "r"(b[1]));
}
// pack x into (hi bf16 | lo bf16 << 16)
__device__ __forceinline__ unsigned packsplit(float x) {
    __nv_bfloat16 h = __float2bfloat16_rn(x);
    float r = x - __bfloat162float(h);
    __nv_bfloat16 l = __float2bfloat16_rn(r);
    unsigned uh, ul;
    uh = *(unsigned short*)&h;
    ul = *(unsigned short*)&l;
    return uh | (ul << 16);
}

// ---------------- FPS: one block per batch, sequential argmax ----------------
__global__ void fps_kernel(const float* __restrict__ p, float* __restrict__ out)
{
    extern __shared__ float sm[];
    float* sx = sm;
    float* sy = sm + NPTS;
    float* sz = sm + 2 * NPTS;
    __shared__ unsigned long long wmax[32];
    __shared__ float cc[3];

    int b = blockIdx.x, t = threadIdx.x;
    const float* pb = p + (size_t)b * NPTS * 3;
    for (int i = t; i < NPTS; i += 1024) {
        sx[i] = pb[3 * i]; sy[i] = pb[3 * i + 1]; sz[i] = pb[3 * i + 2];
    }
    float dmin[4];
#pragma unroll
    for (int j = 0; j < 4; j++) dmin[j] = 1e10f;
    __syncthreads();
    if (t == 0) {
        g_cent[b * NSAMP] = 0;
        out[(size_t)(b * NSAMP) * 3 + 0] = sx[0];
        out[(size_t)(b * NSAMP) * 3 + 1] = sy[0];
        out[(size_t)(b * NSAMP) * 3 + 2] = sz[0];
        cc[0] = sx[0]; cc[1] = sy[0]; cc[2] = sz[0];
    }
    __syncthreads();

    int lane = t & 31, warp = t >> 5;
    for (int it = 1; it < NSAMP; it++) {
        float cx = cc[0], cy = cc[1], cz = cc[2];
        unsigned long long best = 0ull;
#pragma unroll
        for (int j = 0; j < 4; j++) {
            int i = t + j * 1024;
            float dx = __fsub_rn(sx[i], cx);
            float dy = __fsub_rn(sy[i], cy);
            float dz = __fsub_rn(sz[i], cz);
            float d = __fadd_rn(__fadd_rn(__fmul_rn(dx, dx), __fmul_rn(dy, dy)), __fmul_rn(dz, dz));
            dmin[j] = fminf(dmin[j], d);
            unsigned long long key =
                ((unsigned long long)__float_as_uint(dmin[j]) << 32) | (unsigned)(~i);
            best = key > best ? key : best;
        }
#pragma unroll
        for (int o = 16; o; o >>= 1) {
            unsigned long long v = __shfl_xor_sync(0xFFFFFFFFu, best, o);
            best = v > best ? v : best;
        }
        if (lane == 0) wmax[warp] = best;
        __syncthreads();
        if (warp == 0) {
            best = wmax[lane];
#pragma unroll
            for (int o = 16; o; o >>= 1) {
                unsigned long long v = __shfl_xor_sync(0xFFFFFFFFu, best, o);
                best = v > best ? v : best;
            }
            if (lane == 0) {
                int idx = (int)(~(unsigned)(best & 0xFFFFFFFFull));
                g_cent[b * NSAMP + it] = idx;
                size_t o3 = (size_t)(b * NSAMP + it) * 3;
                out[o3 + 0] = sx[idx]; out[o3 + 1] = sy[idx]; out[o3 + 2] = sz[idx];
                cc[0] = sx[idx]; cc[1] = sy[idx]; cc[2] = sz[idx];
            }
        }
        __syncthreads();
    }
}

// ---------------- KNN ----------------
__global__ void knn_kernel(const float* __restrict__ p)
{
    extern __shared__ float sm[];
    float* sx = sm;
    float* sy = sm + NPTS;
    float* sz = sm + 2 * NPTS;

    int b = blockIdx.x >> 5;
    int blk = blockIdx.x & 31;
    const float* pb = p + (size_t)b * NPTS * 3;
    int t = threadIdx.x;
    for (int i = t; i < NPTS; i += 256) {
        sx[i] = pb[3 * i]; sy[i] = pb[3 * i + 1]; sz[i] = pb[3 * i + 2];
    }
    __syncthreads();
    int warp = t >> 5, lane = t & 31;

    for (int q = 0; q < 4; q++) {
        int sc = (blk * 8 + warp) * 4 + q;
        int ci = g_cent[b * NSAMP + sc];
        float cx = sx[ci], cy = sy[ci], cz = sz[ci];
        float normc = __fadd_rn(__fadd_rn(__fmul_rn(cx, cx), __fmul_rn(cy, cy)), __fmul_rn(cz, cz));

        auto makekey = [&](int j) -> unsigned long long {
            float px = sx[j], py = sy[j], pz = sz[j];
            float normp = __fadd_rn(__fadd_rn(__fmul_rn(px, px), __fmul_rn(py, py)), __fmul_rn(pz, pz));
            float dot = __fadd_rn(__fadd_rn(__fmul_rn(cx, px), __fmul_rn(cy, py)), __fmul_rn(cz, pz));
            float d2 = __fsub_rn(__fadd_rn(normc, normp), __fmul_rn(2.0f, dot));
            return ((unsigned long long)fkey(d2) << 32) | (unsigned)j;
        };

        unsigned long long best = makekey(lane);
        unsigned long long thresh;
        {
            unsigned long long mv = best;
#pragma unroll
            for (int o = 16; o; o >>= 1) {
                unsigned long long v = __shfl_xor_sync(0xFFFFFFFFu, mv, o);
                mv = v > mv ? v : mv;
            }
            thresh = mv;
        }
        for (int chunk = 1; chunk < NPTS / 32; chunk++) {
            unsigned long long cand = makekey(chunk * 32 + lane);
            unsigned mask = __ballot_sync(0xFFFFFFFFu, cand < thresh);
            while (mask) {
                int src = __ffs(mask) - 1;
                mask &= mask - 1;
                unsigned long long v = __shfl_sync(0xFFFFFFFFu, cand, src);
                unsigned long long mv = best; int ml = lane;
#pragma unroll
                for (int o = 16; o; o >>= 1) {
                    unsigned long long ov = __shfl_xor_sync(0xFFFFFFFFu, mv, o);
                    int ol = __shfl_xor_sync(0xFFFFFFFFu, ml, o);
                    if (ov > mv) { mv = ov; ml = ol; }
                }
                if (v < mv && lane == ml) best = v;
                thresh = mv;
            }
        }
        g_knn[(size_t)(b * NSAMP + sc) * KNB + lane] = (int)(unsigned)(best & 0xFFFFFFFFull);
    }
}

// ---------------- w12 = w2 @ w1 (256x6) ----------------
__global__ void w12_kernel(const float* __restrict__ w1, const float* __restrict__ w2)
{
    int o = threadIdx.x;
    float acc[6] = {0, 0, 0, 0, 0, 0};
    for (int m = 0; m < 256; m++) {
        float wm = w2[o * 256 + m];
#pragma unroll
        for (int j = 0; j < 6; j++) acc[j] = fmaf(wm, w1[m * 6 + j], acc[j]);
    }
#pragma unroll
    for (int j = 0; j < 6; j++) g_w12[o * 6 + j] = acc[j];
}

// ---------------- weight split: w3[:,256:512] and w4 -> bf16 hi/lo ----------------
__global__ void wsplit_kernel(const float* __restrict__ w3, const float* __restrict__ w4)
{
    int i = blockIdx.x * 256 + threadIdx.x;   // grid covers 512*256 = 131072
    {
        int m = i >> 8, k = i & 255;
        float v = w3[m * 512 + 256 + k];
        __nv_bfloat16 h = __float2bfloat16_rn(v);
        g_wh3[i] = h;
        g_wl3[i] = __float2bfloat16_rn(v - __bfloat162float(h));
    }
    {
        float v = w4[i];                       // 256*512 = 131072 too
        __nv_bfloat16 h = __float2bfloat16_rn(v);
        g_wh4[i] = h;
        g_wl4[i] = __float2bfloat16_rn(v - __bfloat162float(h));
    }
}

// ---------------- stage1: gather + fused conv1+conv2 -> h2 ----------------
__global__ void stage1_kernel(const float* __restrict__ p, const float* __restrict__ f,
                              const float* __restrict__ b2)
{
    __shared__ float x0s[6][KNB];
    __shared__ float ws[256 * 6 + 256];
    int pt = blockIdx.x;
    int b = pt >> 10;
    int t = threadIdx.x;
    for (int i = t; i < 256 * 6 + 256; i += 256)
        ws[i] = (i < 1536) ? g_w12[i] : b2[i - 1536];
    if (t < KNB) {
        int idx = g_knn[(size_t)pt * KNB + t];
        const float* pp = p + (size_t)(b * NPTS + idx) * 3;
        x0s[0][t] = pp[0]; x0s[1][t] = pp[1]; x0s[2][t] = pp[2];
        x0s[3][t] = f[(size_t)(b * 3 + 0) * NPTS + idx];
        x0s[4][t] = f[(size_t)(b * 3 + 1) * NPTS + idx];
        x0s[5][t] = f[(size_t)(b * 3 + 2) * NPTS + idx];
    }
    __syncthreads();
    int k = t & 31, cg = t >> 5;
    float v0 = x0s[0][k], v1 = x0s[1][k], v2 = x0s[2][k],
          v3 = x0s[3][k], v4 = x0s[4][k], v5 = x0s[5][k];
#pragma unroll 4
    for (int m = 0; m < 32; m++) {
        int c = cg * 32 + m;
        float acc = ws[1536 + c];
        acc = fmaf(ws[c * 6 + 0], v0, acc);
        acc = fmaf(ws[c * 6 + 1], v1, acc);
        acc = fmaf(ws[c * 6 + 2], v2, acc);
        acc = fmaf(ws[c * 6 + 3], v3, acc);
        acc = fmaf(ws[c * 6 + 4], v4, acc);
        acc = fmaf(ws[c * 6 + 5], v5, acc);
        g_h2[(size_t)c * NPCOL + (size_t)pt * KNB + k] = acc;
    }
}

// ---------------- BN stats: one block per channel ----------------
__global__ void bnstats_kernel(int which)
{
    const float* src = (which == 1) ? g_h3 : g_h2;   // 0 -> h2, 1 -> h3, 2 -> h4 (in g_h2)
    int c = blockIdx.x;
    int t = threadIdx.x;
    const float4* row = (const float4*)(src + (size_t)c * NPCOL);
    float s = 0.f, q = 0.f;
    for (int i = t; i < NPCOL / 4; i += 256) {
        float4 v = row[i];
        s += v.x + v.y + v.z + v.w;
        q += v.x * v.x + v.y * v.y + v.z * v.z + v.w * v.w;
    }
    __shared__ float rs[256], rq[256];
    rs[t] = s; rq[t] = q;
    __syncthreads();
    for (int o = 128; o; o >>= 1) {
        if (t < o) { rs[t] += rs[t + o]; rq[t] += rq[t + o]; }
        __syncthreads();
    }
    if (t == 0) { g_sum[c] = rs[0]; g_sq[c] = rq[0]; }
}

__global__ void bnfinal_kernel(int which, int n, const float* __restrict__ g,
                               const float* __restrict__ be)
{
    int c = blockIdx.x * blockDim.x + threadIdx.x;
    if (c >= n) return;
    float inv = 1.0f / (float)NPCOL;
    float mean = g_sum[c] * inv;
    float var  = g_sq[c] * inv - mean * mean;
    float s = g[c] * rsqrtf(var + 1e-5f);
    float tt = be[c] - mean * s;
    if (which == 0) { g_s2[c] = s; g_t2[c] = tt; }
    else if (which == 1) { g_s3[c] = s; g_t3[c] = tt; }
    else { g_s4[c] = s; g_t4[c] = tt; }
}

// ---------------- xm = max_k relu(bn2(h2)) ----------------
__global__ void xm_kernel()
{
    int gid = blockIdx.x * 256 + threadIdx.x;
    int c = gid >> 12, pt = gid & 4095;
    float s = g_s2[c], t = g_t2[c];
    const float4* src = (const float4*)(g_h2 + (size_t)c * NPCOL + (size_t)pt * KNB);
    float m = 0.f;
#pragma unroll
    for (int i = 0; i < 8; i++) {
        float4 v = src[i];
        m = fmaxf(m, fmaxf(fmaxf(fmaf(v.x, s, t), fmaf(v.y, s, t)),
                           fmaxf(fmaf(v.z, s, t), fmaf(v.w, s, t))));
    }
    g_xm[c * NCENT + pt] = m;
}

// ---------------- in-place activation split: fp32 h -> packed (hi|lo<<16) ----------------
__global__ void split_kernel(int which)   // 0: h2 (256 ch), 1: h3 (512 ch)
{
    float* src = which ? g_h3 : g_h2;
    const float* S = which ? g_s3 : g_s2;
    const float* T = which ? g_t3 : g_t2;
    size_t i = (size_t)blockIdx.x * 256 + threadIdx.x;   // one thread = 8 elems
    int c = (int)(i >> 14);                              // NPCOL/8 = 16384 threads per channel
    float s = S[c], t = T[c];
    const float4* sp = (const float4*)src + i * 2;
    float4 v0 = sp[0], v1 = sp[1];
    uint4 o0, o1;
    o0.x = packsplit(fmaxf(fmaf(v0.x, s, t), 0.f));
    o0.y = packsplit(fmaxf(fmaf(v0.y, s, t), 0.f));
    o0.z = packsplit(fmaxf(fmaf(v0.z, s, t), 0.f));
    o0.w = packsplit(fmaxf(fmaf(v0.w, s, t), 0.f));
    o1.x = packsplit(fmaxf(fmaf(v1.x, s, t), 0.f));
    o1.y = packsplit(fmaxf(fmaf(v1.y, s, t), 0.f));
    o1.z = packsplit(fmaxf(fmaf(v1.z, s, t), 0.f));
    o1.w = packsplit(fmaxf(fmaf(v1.w, s, t), 0.f));
    uint4* dp = (uint4*)src + i * 2;
    dp[0] = o0;
    dp[1] = o1;
}

// ---------------- C1(512 x 4096) = w3[:, 0:256] @ xm(256 x 4096) ----------------
__global__ __launch_bounds__(256, 2) void c1_kernel(const float* __restrict__ w3)
{
    __shared__ __align__(16) float As[16][128];
    __shared__ __align__(16) float Bs[16][128];
    int n0 = blockIdx.x * 128, m0 = blockIdx.y * 128;
    int tid = threadIdx.x, tx = tid & 15, ty = tid >> 4;
    float acc[8][8];
#pragma unroll
    for (int i = 0; i < 8; i++)
#pragma unroll
        for (int j = 0; j < 8; j++) acc[i][j] = 0.f;

    for (int k0 = 0; k0 < 256; k0 += 16) {
        {
            int m = tid >> 1, kq = (tid & 1) * 8;
            const float4* ap = (const float4*)(w3 + (size_t)(m0 + m) * 512 + k0 + kq);
            float4 a0 = ap[0], a1 = ap[1];
            As[kq + 0][m] = a0.x; As[kq + 1][m] = a0.y; As[kq + 2][m] = a0.z; As[kq + 3][m] = a0.w;
            As[kq + 4][m] = a1.x; As[kq + 5][m] = a1.y; As[kq + 6][m] = a1.z; As[kq + 7][m] = a1.w;
        }
        {
            int r = tid >> 4, c8 = (tid & 15) * 8;
            const float4* bp = (const float4*)(g_xm + (size_t)(k0 + r) * NCENT + n0 + c8);
            float4 b0 = bp[0], b1 = bp[1];
            *(float4*)&Bs[r][c8] = b0;
            *(float4*)&Bs[r][c8 + 4] = b1;
        }
        __syncthreads();
#pragma unroll
        for (int kk = 0; kk < 16; kk++) {
            float a[8], bb[8];
            *(float4*)(&a[0]) = *(const float4*)(&As[kk][ty * 8]);
            *(float4*)(&a[4]) = *(const float4*)(&As[kk][ty * 8 + 4]);
            *(float4*)(&bb[0]) = *(const float4*)(&Bs[kk][tx * 8]);
            *(float4*)(&bb[4]) = *(const float4*)(&Bs[kk][tx * 8 + 4]);
#pragma unroll
            for (int i = 0; i < 8; i++)
#pragma unroll
                for (int j = 0; j < 8; j++)
                    acc[i][j] = fmaf(a[i], bb[j], acc[i][j]);
        }
        __syncthreads();
    }
#pragma unroll
    for (int i = 0; i < 8; i++) {
        float* cp = g_c1 + (size_t)(m0 + ty * 8 + i) * NCENT + n0 + tx * 8;
        *(float4*)cp = make_float4(acc[i][0], acc[i][1], acc[i][2], acc[i][3]);
        *(float4*)(cp + 4) = make_float4(acc[i][4], acc[i][5], acc[i][6], acc[i][7]);
    }
}

// ---------------- bf16 split-precision tensor-core GEMM ----------------
// mode 0: g_h3(512 x NPCOL) = W3b @ split(h2)  + c1 broadcast   (K=256)
// mode 1: g_h2(256 x NPCOL) = W4  @ split(h3)                   (K=512)
// acc += Ah*Bh + Ah*Bl + Al*Bh   (fp32 accumulate)
#define APAD 40    // A smem row stride (bf16): 80B
#define BPAD 136   // B smem row stride (bf16): 272B -> conflict-free ldmatrix
__global__ __launch_bounds__(256) void gemm_mma(int mode)
{
    __shared__ __align__(16) __nv_bfloat16 Ah[128 * APAD], Al[128 * APAD];
    __shared__ __align__(16) __nv_bfloat16 Bh[32 * BPAD],  Bl[32 * BPAD];

    const int K = (mode == 0) ? 256 : 512;
    const __nv_bfloat16* __restrict__ Wh = (mode == 0) ? g_wh3 : g_wh4;
    const __nv_bfloat16* __restrict__ Wl = (mode == 0) ? g_wl3 : g_wl4;
    const float* __restrict__ Hsrc = (mode == 0) ? g_h2 : g_h3;   // packed words
    int m0 = blockIdx.x * 128;
    int n0 = blockIdx.y * 128;
    int tid = threadIdx.x, lane = tid & 31, wid = tid >> 5;
    int wm = (wid >> 2) * 64;     // warp m offset (0/64)
    int wn = (wid & 3) * 32;      // warp n offset (0/32/64/96)

    float acc[4][4][4];
#pragma unroll
    for (int i = 0; i < 4; i++)
#pragma unroll
        for (int j = 0; j < 4; j++)
#pragma unroll
            for (int q = 0; q < 4; q++) acc[i][j][q] = 0.f;

    int ar = tid >> 2, ac = (tid & 3) * 8;     // A tile: rows ar, ar+64; 8 bf16 each
    int br = tid >> 4, bc = (tid & 15) * 8;    // B tile: rows br, br+16; 8 elems each

    // fragment address components
    int a_row = wm + (lane & 7) + ((lane >> 3) & 1) * 8;    // + i*16
    int a_col = (lane >> 4) * 8;                            // + kk*16
    int b_row = (lane & 7) + ((lane >> 3) & 1) * 8;         // + kk*16
    int b_col = wn + (lane >> 4) * 8;                       // + jj*16

    for (int k0 = 0; k0 < K; k0 += 32) {
        if (k0) __syncthreads();
#pragma unroll
        for (int h = 0; h < 2; h++) {
            int m = ar + h * 64;
            size_t go = (size_t)(m0 + m) * K + k0 + ac;
            *(uint4*)(Ah + m * APAD + ac) = *(const uint4*)(Wh + go);
            *(uint4*)(Al + m * APAD + ac) = *(const uint4*)(Wl + go);
        }
#pragma unroll
        for (int h = 0; h < 2; h++) {
            int r = br + h * 16;
            size_t go = (size_t)(k0 + r) * NPCOL + n0 + bc;
            const uint4* sp = (const uint4*)(Hsrc + go);
            uint4 e0 = sp[0], e1 = sp[1];      // 8 packed elems
            uint4 hv, lv;
            hv.x = __byte_perm(e0.x, e0.y, 0x5410); lv.x = __byte_perm(e0.x, e0.y, 0x7632);
            hv.y = __byte_perm(e0.z, e0.w, 0x5410); lv.y = __byte_perm(e0.z, e0.w, 0x7632);
            hv.z = __byte_perm(e1.x, e1.y, 0x5410); lv.z = __byte_perm(e1.x, e1.y, 0x7632);
            hv.w = __byte_perm(e1.z, e1.w, 0x5410); lv.w = __byte_perm(e1.z, e1.w, 0x7632);
            *(uint4*)(Bh + r * BPAD + bc) = hv;
            *(uint4*)(Bl + r * BPAD + bc) = lv;
        }
        __syncthreads();

#pragma unroll
        for (int kk = 0; kk < 2; kk++) {
            unsigned ah[4][4], al[4][4], bh[4][2], bl[4][2];
#pragma unroll
            for (int i = 0; i < 4; i++) {
                int off = (a_row + i * 16) * APAD + a_col + kk * 16;
                ldsm4(ah[i], sm_u32(Ah + off));
                ldsm4(al[i], sm_u32(Al + off));
            }
#pragma unroll
            for (int jj = 0; jj < 2; jj++) {
                int off = (b_row + kk * 16) * BPAD + b_col + jj * 16;
                unsigned r4[4];
                ldsm4t(r4, sm_u32(Bh + off));
                bh[jj * 2][0] = r4[0]; bh[jj * 2][1] = r4[1];
                bh[jj * 2 + 1][0] = r4[2]; bh[jj * 2 + 1][1] = r4[3];
                ldsm4t(r4, sm_u32(Bl + off));
                bl[jj * 2][0] = r4[0]; bl[jj * 2][1] = r4[1];
                bl[jj * 2 + 1][0] = r4[2]; bl[jj * 2 + 1][1] = r4[3];
            }
#pragma unroll
            for (int i = 0; i < 4; i++)
#pragma unroll
                for (int j = 0; j < 4; j++) {
                    mma16816(acc[i][j], ah[i], bh[j]);
                    mma16816(acc[i][j], ah[i], bl[j]);
                    mma16816(acc[i][j], al[i], bh[j]);
                }
        }
    }

    // epilogue
    int g = lane >> 2, tg = lane & 3;
    float* C = (mode == 0) ? g_h3 : g_h2;
    if (mode == 0) {
        int pt = (n0 + wn) >> 5;   // warp's 32 n-cols = exactly one point
#pragma unroll
        for (int i = 0; i < 4; i++) {
            int m = m0 + wm + i * 16 + g;
            float cv0 = g_c1[(size_t)m * NCENT + pt];
            float cv1 = g_c1[(size_t)(m + 8) * NCENT + pt];
#pragma unroll
            for (int j = 0; j < 4; j++) {
                acc[i][j][0] += cv0; acc[i][j][1] += cv0;
                acc[i][j][2] += cv1; acc[i][j][3] += cv1;
            }
        }
    }
#pragma unroll
    for (int i = 0; i < 4; i++) {
        int m = m0 + wm + i * 16 + g;
#pragma unroll
        for (int j = 0; j < 4; j++) {
            int n = n0 + wn + j * 8 + 2 * tg;
            *(float2*)(C + (size_t)m * NPCOL + n)       = make_float2(acc[i][j][0], acc[i][j][1]);
            *(float2*)(C + (size_t)(m + 8) * NPCOL + n) = make_float2(acc[i][j][2], acc[i][j][3]);
        }
    }
}

// ---------------- final: out_feat = max_k relu(bn4(h4)) ----------------
__global__ void final_kernel(float* __restrict__ out)
{
    int gid = blockIdx.x * 256 + threadIdx.x;
    int c = gid >> 12, pt = gid & 4095;
    float s = g_s4[c], t = g_t4[c];
    const float4* src = (const float4*)(g_h2 + (size_t)c * NPCOL + (size_t)pt * KNB);
    float m = 0.f;
#pragma unroll
    for (int i = 0; i < 8; i++) {
        float4 v = src[i];
        m = fmaxf(m, fmaxf(fmaxf(fmaf(v.x, s, t), fmaf(v.y, s, t)),
                           fmaxf(fmaf(v.z, s, t), fmaf(v.w, s, t))));
    }
    int b = pt >> 10, sIdx = pt & 1023;
    out[12288 + (size_t)((b << 8) + c) * 1024 + sIdx] = m;
}

// ---------------- launch ----------------
extern "C" void kernel_launch(void* const* d_in, const int* in_sizes, int n_in,
                              void* d_out, int out_size)
{
    const float* p   = (const float*)d_in[0];
    const float* f   = (const float*)d_in[1];
    const float* w1  = (const float*)d_in[2];
    const float* w2  = (const float*)d_in[3];
    const float* b2  = (const float*)d_in[4];
    const float* g2  = (const float*)d_in[5];
    const float* be2 = (const float*)d_in[6];
    const float* w3  = (const float*)d_in[7];
    const float* g3  = (const float*)d_in[8];
    const float* be3 = (const float*)d_in[9];
    const float* w4  = (const float*)d_in[10];
    const float* g4  = (const float*)d_in[11];
    const float* be4 = (const float*)d_in[12];
    float* out = (float*)d_out;

    cudaFuncSetAttribute(fps_kernel, cudaFuncAttributeMaxDynamicSharedMemorySize, 65536);
    cudaFuncSetAttribute(knn_kernel, cudaFuncAttributeMaxDynamicSharedMemorySize, 65536);

    w12_kernel<<<1, 256>>>(w1, w2);
    wsplit_kernel<<<512, 256>>>(w3, w4);
    fps_kernel<<<BATCH, 1024, NPTS * 3 * sizeof(float)>>>(p, out);
    knn_kernel<<<BATCH * 32, 256, NPTS * 3 * sizeof(float)>>>(p);
    stage1_kernel<<<NCENT, 256>>>(p, f, b2);

    bnstats_kernel<<<256, 256>>>(0);
    bnfinal_kernel<<<1, 256>>>(0, 256, g2, be2);
    xm_kernel<<<NCENT, 256>>>();
    c1_kernel<<<dim3(NCENT / 128, 512 / 128), 256>>>(w3);
    split_kernel<<<(256 * (NPCOL / 8)) / 256, 256>>>(0);   // h2 -> packed split, in place

    gemm_mma<<<dim3(512 / 128, NPCOL / 128), 256>>>(0);
    bnstats_kernel<<<512, 256>>>(1);
    bnfinal_kernel<<<2, 256>>>(1, 512, g3, be3);
    split_kernel<<<(512 * (NPCOL / 8)) / 256, 256>>>(1);   // h3 -> packed split, in place

    gemm_mma<<<dim3(256 / 128, NPCOL / 128), 256>>>(1);
    bnstats_kernel<<<256, 256>>>(2);
    bnfinal_kernel<<<1, 256>>>(2, 256, g4, be4);

    final_kernel<<<NCENT, 256>>>(out);
}

// round 6
// speedup vs baseline: 2.7753x; 1.0557x over previous
#include <cuda_runtime.h>
#include <cuda_bf16.h>
#include <cstdint>

#define BATCH 4
#define NPTS  4096
#define NSAMP 1024
#define KNB   32
#define NCENT 4096          // BATCH*NSAMP
#define NPCOL 131072        // NCENT*KNB

// ---------------- scratch (static device memory: keep total < ~400MB) ----------------
__device__ int   g_cent[NCENT];
__device__ int   g_knn[NCENT * KNB];
__device__ float g_w12[256 * 6];
__device__ float g_h2[(size_t)256 * NPCOL];   // 128 MB: h2 fp32 -> in-place split -> h4 fp32
__device__ float g_xm[256 * NCENT];           // 4 MB
__device__ float g_c1[(size_t)512 * NCENT];   // 8 MB  (w3[:, :256] @ xm)
__device__ float g_h3[(size_t)512 * NPCOL];   // 256 MB: h3 fp32 -> in-place split
__device__ __nv_bfloat16 g_wh3[512 * 256], g_wl3[512 * 256];
__device__ __nv_bfloat16 g_wh4[256 * 512], g_wl4[256 * 512];
__device__ float g_sum[512], g_sq[512];
__device__ float g_s2[256], g_t2[256];
__device__ float g_s3[512], g_t3[512];
__device__ float g_s4[256], g_t4[256];

// ---------------- helpers ----------------
__device__ __forceinline__ unsigned fkey(float x) {
    unsigned u = __float_as_uint(x);
    u ^= (u & 0x80000000u) ? 0xFFFFFFFFu : 0x80000000u;
    return u;
}
__device__ __forceinline__ unsigned sm_u32(const void* p) {
    return (unsigned)__cvta_generic_to_shared(p);
}
__device__ __forceinline__ void cpasync16(void* smem, const void* g) {
    asm volatile("cp.async.cg.shared.global [%0], [%1], 16;" :: "r"(sm_u32(smem)), "l"(g));
}
__device__ __forceinline__ void ldsm4(unsigned r[4], unsigned addr) {
    asm volatile("ldmatrix.sync.aligned.m8n8.x4.shared.b16 {%0,%1,%2,%3}, [%4];"
                 : "=r"(r[0]), "=r"(r[1]), "=r"(r[2]), "=r"(r[3]) : "r"(addr));
}
__device__ __forceinline__ void ldsm4t(unsigned r[4], unsigned addr) {
    asm volatile("ldmatrix.sync.aligned.m8n8.x4.trans.shared.b16 {%0,%1,%2,%3}, [%4];"
                 : "=r"(r[0]), "=r"(r[1]), "=r"(r[2]), "=r"(r[3]) : "r"(addr));
}
__device__ __forceinline__ void mma16816(float d[4], const unsigned a[4], const unsigned b[2]) {
    asm volatile("mma.sync.aligned.m16n8k16.row.col.f32.bf16.bf16.f32 "
                 "{%0,%1,%2,%3}, {%4,%5,%6,%7}, {%8,%9}, {%0,%1,%2,%3};"
                 : "+f"(d[0]), "+f"(d[1]), "+f"(d[2]), "+f"(d[3])
                 : "r"(a[0]), "r"(a[1]), "r"(a[2]), "r"(a[3]), "r"(b[0]), "r"(b[1]));
}
// pack x into (hi bf16 | lo bf16 << 16)
__device__ __forceinline__ unsigned packsplit(float x) {
    __nv_bfloat16 h = __float2bfloat16_rn(x);
    float r = x - __bfloat162float(h);
    __nv_bfloat16 l = __float2bfloat16_rn(r);
    unsigned uh = *(unsigned short*)&h, ul = *(unsigned short*)&l;
    return uh | (ul << 16);
}

// ---------------- FPS: one block per batch, sequential argmax ----------------
__global__ void fps_kernel(const float* __restrict__ p, float* __restrict__ out)
{
    extern __shared__ float sm[];
    float* sx = sm;
    float* sy = sm + NPTS;
    float* sz = sm + 2 * NPTS;
    __shared__ unsigned long long wmax[32];
    __shared__ float cc[3];

    int b = blockIdx.x, t = threadIdx.x;
    const float* pb = p + (size_t)b * NPTS * 3;
    for (int i = t; i < NPTS; i += 1024) {
        sx[i] = pb[3 * i]; sy[i] = pb[3 * i + 1]; sz[i] = pb[3 * i + 2];
    }
    float dmin[4];
#pragma unroll
    for (int j = 0; j < 4; j++) dmin[j] = 1e10f;
    __syncthreads();
    if (t == 0) {
        g_cent[b * NSAMP] = 0;
        out[(size_t)(b * NSAMP) * 3 + 0] = sx[0];
        out[(size_t)(b * NSAMP) * 3 + 1] = sy[0];
        out[(size_t)(b * NSAMP) * 3 + 2] = sz[0];
        cc[0] = sx[0]; cc[1] = sy[0]; cc[2] = sz[0];
    }
    __syncthreads();

    int lane = t & 31, warp = t >> 5;
    for (int it = 1; it < NSAMP; it++) {
        float cx = cc[0], cy = cc[1], cz = cc[2];
        unsigned long long best = 0ull;
#pragma unroll
        for (int j = 0; j < 4; j++) {
            int i = t + j * 1024;
            float dx = __fsub_rn(sx[i], cx);
            float dy = __fsub_rn(sy[i], cy);
            float dz = __fsub_rn(sz[i], cz);
            float d = __fadd_rn(__fadd_rn(__fmul_rn(dx, dx), __fmul_rn(dy, dy)), __fmul_rn(dz, dz));
            dmin[j] = fminf(dmin[j], d);
            unsigned long long key =
                ((unsigned long long)__float_as_uint(dmin[j]) << 32) | (unsigned)(~i);
            best = key > best ? key : best;
        }
#pragma unroll
        for (int o = 16; o; o >>= 1) {
            unsigned long long v = __shfl_xor_sync(0xFFFFFFFFu, best, o);
            best = v > best ? v : best;
        }
        if (lane == 0) wmax[warp] = best;
        __syncthreads();
        if (warp == 0) {
            best = wmax[lane];
#pragma unroll
            for (int o = 16; o; o >>= 1) {
                unsigned long long v = __shfl_xor_sync(0xFFFFFFFFu, best, o);
                best = v > best ? v : best;
            }
            if (lane == 0) {
                int idx = (int)(~(unsigned)(best & 0xFFFFFFFFull));
                g_cent[b * NSAMP + it] = idx;
                size_t o3 = (size_t)(b * NSAMP + it) * 3;
                out[o3 + 0] = sx[idx]; out[o3 + 1] = sy[idx]; out[o3 + 2] = sz[idx];
                cc[0] = sx[idx]; cc[1] = sy[idx]; cc[2] = sz[idx];
            }
        }
        __syncthreads();
    }
}

// ---------------- KNN: 128 blocks/batch, 8 warps/block, 1 centroid/warp ----------------
__global__ void knn_kernel(const float* __restrict__ p)
{
    extern __shared__ float sm[];
    float* sx = sm;
    float* sy = sm + NPTS;
    float* sz = sm + 2 * NPTS;

    int b = blockIdx.x >> 7;
    int blk = blockIdx.x & 127;
    const float* pb = p + (size_t)b * NPTS * 3;
    int t = threadIdx.x;
    for (int i = t; i < NPTS; i += 256) {
        sx[i] = pb[3 * i]; sy[i] = pb[3 * i + 1]; sz[i] = pb[3 * i + 2];
    }
    __syncthreads();
    int warp = t >> 5, lane = t & 31;

    int sc = blk * 8 + warp;             // centroid index within batch
    int ci = g_cent[b * NSAMP + sc];
    float cx = sx[ci], cy = sy[ci], cz = sz[ci];
    float normc = __fadd_rn(__fadd_rn(__fmul_rn(cx, cx), __fmul_rn(cy, cy)), __fmul_rn(cz, cz));

    auto makekey = [&](int j) -> unsigned long long {
        float px = sx[j], py = sy[j], pz = sz[j];
        float normp = __fadd_rn(__fadd_rn(__fmul_rn(px, px), __fmul_rn(py, py)), __fmul_rn(pz, pz));
        float dot = __fadd_rn(__fadd_rn(__fmul_rn(cx, px), __fmul_rn(cy, py)), __fmul_rn(cz, pz));
        float d2 = __fsub_rn(__fadd_rn(normc, normp), __fmul_rn(2.0f, dot));
        return ((unsigned long long)fkey(d2) << 32) | (unsigned)j;
    };

    unsigned long long best = makekey(lane);
    unsigned long long thresh;
    {
        unsigned long long mv = best;
#pragma unroll
        for (int o = 16; o; o >>= 1) {
            unsigned long long v = __shfl_xor_sync(0xFFFFFFFFu, mv, o);
            mv = v > mv ? v : mv;
        }
        thresh = mv;
    }
    for (int chunk = 1; chunk < NPTS / 32; chunk++) {
        unsigned long long cand = makekey(chunk * 32 + lane);
        unsigned mask = __ballot_sync(0xFFFFFFFFu, cand < thresh);
        while (mask) {
            int src = __ffs(mask) - 1;
            mask &= mask - 1;
            unsigned long long v = __shfl_sync(0xFFFFFFFFu, cand, src);
            unsigned long long mv = best; int ml = lane;
#pragma unroll
            for (int o = 16; o; o >>= 1) {
                unsigned long long ov = __shfl_xor_sync(0xFFFFFFFFu, mv, o);
                int ol = __shfl_xor_sync(0xFFFFFFFFu, ml, o);
                if (ov > mv) { mv = ov; ml = ol; }
            }
            if (v < mv && lane == ml) best = v;
            thresh = mv;
        }
    }
    g_knn[(size_t)(b * NSAMP + sc) * KNB + lane] = (int)(unsigned)(best & 0xFFFFFFFFull);
}

// ---------------- w12 = w2 @ w1 (256x6) ----------------
__global__ void w12_kernel(const float* __restrict__ w1, const float* __restrict__ w2)
{
    int o = threadIdx.x;
    float acc[6] = {0, 0, 0, 0, 0, 0};
    for (int m = 0; m < 256; m++) {
        float wm = w2[o * 256 + m];
#pragma unroll
        for (int j = 0; j < 6; j++) acc[j] = fmaf(wm, w1[m * 6 + j], acc[j]);
    }
#pragma unroll
    for (int j = 0; j < 6; j++) g_w12[o * 6 + j] = acc[j];
}

// ---------------- weight split: w3[:,256:512] and w4 -> bf16 hi/lo ----------------
__global__ void wsplit_kernel(const float* __restrict__ w3, const float* __restrict__ w4)
{
    int i = blockIdx.x * 256 + threadIdx.x;   // 512*256 = 131072
    {
        int m = i >> 8, k = i & 255;
        float v = w3[m * 512 + 256 + k];
        __nv_bfloat16 h = __float2bfloat16_rn(v);
        g_wh3[i] = h;
        g_wl3[i] = __float2bfloat16_rn(v - __bfloat162float(h));
    }
    {
        float v = w4[i];
        __nv_bfloat16 h = __float2bfloat16_rn(v);
        g_wh4[i] = h;
        g_wl4[i] = __float2bfloat16_rn(v - __bfloat162float(h));
    }
}

// ---------------- stage1: gather + fused conv1+conv2 -> h2 ----------------
__global__ void stage1_kernel(const float* __restrict__ p, const float* __restrict__ f,
                              const float* __restrict__ b2)
{
    __shared__ float x0s[6][KNB];
    __shared__ float ws[256 * 6 + 256];
    int pt = blockIdx.x;
    int b = pt >> 10;
    int t = threadIdx.x;
    for (int i = t; i < 256 * 6 + 256; i += 256)
        ws[i] = (i < 1536) ? g_w12[i] : b2[i - 1536];
    if (t < KNB) {
        int idx = g_knn[(size_t)pt * KNB + t];
        const float* pp = p + (size_t)(b * NPTS + idx) * 3;
        x0s[0][t] = pp[0]; x0s[1][t] = pp[1]; x0s[2][t] = pp[2];
        x0s[3][t] = f[(size_t)(b * 3 + 0) * NPTS + idx];
        x0s[4][t] = f[(size_t)(b * 3 + 1) * NPTS + idx];
        x0s[5][t] = f[(size_t)(b * 3 + 2) * NPTS + idx];
    }
    __syncthreads();
    int k = t & 31, cg = t >> 5;
    float v0 = x0s[0][k], v1 = x0s[1][k], v2 = x0s[2][k],
          v3 = x0s[3][k], v4 = x0s[4][k], v5 = x0s[5][k];
#pragma unroll 4
    for (int m = 0; m < 32; m++) {
        int c = cg * 32 + m;
        float acc = ws[1536 + c];
        acc = fmaf(ws[c * 6 + 0], v0, acc);
        acc = fmaf(ws[c * 6 + 1], v1, acc);
        acc = fmaf(ws[c * 6 + 2], v2, acc);
        acc = fmaf(ws[c * 6 + 3], v3, acc);
        acc = fmaf(ws[c * 6 + 4], v4, acc);
        acc = fmaf(ws[c * 6 + 5], v5, acc);
        g_h2[(size_t)c * NPCOL + (size_t)pt * KNB + k] = acc;
    }
}

// ---------------- BN stats pass (used for h2 only now) ----------------
__global__ void bnstats_kernel(int which)
{
    const float* src = (which == 1) ? g_h3 : g_h2;
    int c = blockIdx.x;
    int t = threadIdx.x;
    const float4* row = (const float4*)(src + (size_t)c * NPCOL);
    float s = 0.f, q = 0.f;
    for (int i = t; i < NPCOL / 4; i += 256) {
        float4 v = row[i];
        s += v.x + v.y + v.z + v.w;
        q += v.x * v.x + v.y * v.y + v.z * v.z + v.w * v.w;
    }
    __shared__ float rs[256], rq[256];
    rs[t] = s; rq[t] = q;
    __syncthreads();
    for (int o = 128; o; o >>= 1) {
        if (t < o) { rs[t] += rs[t + o]; rq[t] += rq[t + o]; }
        __syncthreads();
    }
    if (t == 0) { g_sum[c] = rs[0]; g_sq[c] = rq[0]; }
}

__global__ void zerostats_kernel()
{
    int c = threadIdx.x;
    g_sum[c] = 0.f; g_sq[c] = 0.f;
}

__global__ void bnfinal_kernel(int which, int n, const float* __restrict__ g,
                               const float* __restrict__ be)
{
    int c = blockIdx.x * blockDim.x + threadIdx.x;
    if (c >= n) return;
    float inv = 1.0f / (float)NPCOL;
    float mean = g_sum[c] * inv;
    float var  = g_sq[c] * inv - mean * mean;
    float s = g[c] * rsqrtf(var + 1e-5f);
    float tt = be[c] - mean * s;
    if (which == 0) { g_s2[c] = s; g_t2[c] = tt; }
    else if (which == 1) { g_s3[c] = s; g_t3[c] = tt; }
    else { g_s4[c] = s; g_t4[c] = tt; }
}

// ---------------- split0: h2 -> packed split (in place) + xm (max over k) ----------------
__global__ void split0_kernel()
{
    int i = blockIdx.x * 256 + threadIdx.x;      // 256ch * 4096pt
    int c = i >> 12, pt = i & 4095;
    float s = g_s2[c], t = g_t2[c];
    float* base = g_h2 + (size_t)c * NPCOL + (size_t)pt * KNB;
    float m = 0.f;
#pragma unroll
    for (int u = 0; u < 8; u++) {
        float4 v = ((const float4*)base)[u];
        float a0 = fmaxf(fmaf(v.x, s, t), 0.f);
        float a1 = fmaxf(fmaf(v.y, s, t), 0.f);
        float a2 = fmaxf(fmaf(v.z, s, t), 0.f);
        float a3 = fmaxf(fmaf(v.w, s, t), 0.f);
        m = fmaxf(m, fmaxf(fmaxf(a0, a1), fmaxf(a2, a3)));
        uint4 o;
        o.x = packsplit(a0); o.y = packsplit(a1); o.z = packsplit(a2); o.w = packsplit(a3);
        ((uint4*)base)[u] = o;
    }
    g_xm[c * NCENT + pt] = m;
}

// ---------------- split1: h3 -> packed split (in place) ----------------
__global__ void split1_kernel()
{
    size_t i = (size_t)blockIdx.x * 256 + threadIdx.x;   // one thread = 8 elems
    int c = (int)(i >> 14);
    float s = g_s3[c], t = g_t3[c];
    float* src = g_h3;
    const float4* sp = (const float4*)src + i * 2;
    float4 v0 = sp[0], v1 = sp[1];
    uint4 o0, o1;
    o0.x = packsplit(fmaxf(fmaf(v0.x, s, t), 0.f));
    o0.y = packsplit(fmaxf(fmaf(v0.y, s, t), 0.f));
    o0.z = packsplit(fmaxf(fmaf(v0.z, s, t), 0.f));
    o0.w = packsplit(fmaxf(fmaf(v0.w, s, t), 0.f));
    o1.x = packsplit(fmaxf(fmaf(v1.x, s, t), 0.f));
    o1.y = packsplit(fmaxf(fmaf(v1.y, s, t), 0.f));
    o1.z = packsplit(fmaxf(fmaf(v1.z, s, t), 0.f));
    o1.w = packsplit(fmaxf(fmaf(v1.w, s, t), 0.f));
    uint4* dp = (uint4*)src + i * 2;
    dp[0] = o0;
    dp[1] = o1;
}

// ---------------- C1(512 x 4096) = w3[:, 0:256] @ xm(256 x 4096) ----------------
__global__ __launch_bounds__(256, 2) void c1_kernel(const float* __restrict__ w3)
{
    __shared__ __align__(16) float As[16][128];
    __shared__ __align__(16) float Bs[16][128];
    int n0 = blockIdx.x * 128, m0 = blockIdx.y * 128;
    int tid = threadIdx.x, tx = tid & 15, ty = tid >> 4;
    float acc[8][8];
#pragma unroll
    for (int i = 0; i < 8; i++)
#pragma unroll
        for (int j = 0; j < 8; j++) acc[i][j] = 0.f;

    for (int k0 = 0; k0 < 256; k0 += 16) {
        {
            int m = tid >> 1, kq = (tid & 1) * 8;
            const float4* ap = (const float4*)(w3 + (size_t)(m0 + m) * 512 + k0 + kq);
            float4 a0 = ap[0], a1 = ap[1];
            As[kq + 0][m] = a0.x; As[kq + 1][m] = a0.y; As[kq + 2][m] = a0.z; As[kq + 3][m] = a0.w;
            As[kq + 4][m] = a1.x; As[kq + 5][m] = a1.y; As[kq + 6][m] = a1.z; As[kq + 7][m] = a1.w;
        }
        {
            int r = tid >> 4, c8 = (tid & 15) * 8;
            const float4* bp = (const float4*)(g_xm + (size_t)(k0 + r) * NCENT + n0 + c8);
            float4 b0 = bp[0], b1 = bp[1];
            *(float4*)&Bs[r][c8] = b0;
            *(float4*)&Bs[r][c8 + 4] = b1;
        }
        __syncthreads();
#pragma unroll
        for (int kk = 0; kk < 16; kk++) {
            float a[8], bb[8];
            *(float4*)(&a[0]) = *(const float4*)(&As[kk][ty * 8]);
            *(float4*)(&a[4]) = *(const float4*)(&As[kk][ty * 8 + 4]);
            *(float4*)(&bb[0]) = *(const float4*)(&Bs[kk][tx * 8]);
            *(float4*)(&bb[4]) = *(const float4*)(&Bs[kk][tx * 8 + 4]);
#pragma unroll
            for (int i = 0; i < 8; i++)
#pragma unroll
                for (int j = 0; j < 8; j++)
                    acc[i][j] = fmaf(a[i], bb[j], acc[i][j]);
        }
        __syncthreads();
    }
#pragma unroll
    for (int i = 0; i < 8; i++) {
        float* cp = g_c1 + (size_t)(m0 + ty * 8 + i) * NCENT + n0 + tx * 8;
        *(float4*)cp = make_float4(acc[i][0], acc[i][1], acc[i][2], acc[i][3]);
        *(float4*)(cp + 4) = make_float4(acc[i][4], acc[i][5], acc[i][6], acc[i][7]);
    }
}

// ---------------- pipelined bf16 split-precision tensor-core GEMM + fused BN stats ----------------
// mode 0: g_h3(512 x NPCOL) = W3b @ split(h2)  + c1 broadcast   (K=256)
// mode 1: g_h2(256 x NPCOL) = W4  @ split(h3)                   (K=512)
#define APAD 40
#define BPAD 136
#define ASTAGE (128 * APAD)
#define BSTAGE (32 * BPAD)
#define GSMEM ((4 * ASTAGE + 4 * BSTAGE) * 2 + 256 * 4)   // 76800 B
__global__ __launch_bounds__(256) void gemm_mma(int mode)
{
    extern __shared__ __align__(16) __nv_bfloat16 dyn[];
    __nv_bfloat16* Ah = dyn;
    __nv_bfloat16* Al = Ah + 2 * ASTAGE;
    __nv_bfloat16* Bh = Al + 2 * ASTAGE;
    __nv_bfloat16* Bl = Bh + 2 * BSTAGE;
    float* ssum = (float*)(Bl + 2 * BSTAGE);
    float* ssq  = ssum + 128;

    const int K = (mode == 0) ? 256 : 512;
    const __nv_bfloat16* __restrict__ Wh = (mode == 0) ? g_wh3 : g_wh4;
    const __nv_bfloat16* __restrict__ Wl = (mode == 0) ? g_wl3 : g_wl4;
    const float* __restrict__ Hsrc = (mode == 0) ? g_h2 : g_h3;   // packed words
    int m0 = blockIdx.x * 128;
    int n0 = blockIdx.y * 128;
    int tid = threadIdx.x, lane = tid & 31, wid = tid >> 5;
    int wm = (wid >> 2) * 64;
    int wn = (wid & 3) * 32;

    if (tid < 128) { ssum[tid] = 0.f; ssq[tid] = 0.f; }

    float acc[4][4][4];
#pragma unroll
    for (int i = 0; i < 4; i++)
#pragma unroll
        for (int j = 0; j < 4; j++)
#pragma unroll
            for (int q = 0; q < 4; q++) acc[i][j][q] = 0.f;

    int ar = tid >> 2, ac = (tid & 3) * 8;
    int br = tid >> 4, bc = (tid & 15) * 8;

    int a_row = wm + (lane & 7) + ((lane >> 3) & 1) * 8;
    int a_col = (lane >> 4) * 8;
    int b_row = (lane & 7) + ((lane >> 3) & 1) * 8;
    int b_col = wn + (lane >> 4) * 8;

    uint4 e[2][2];
    auto copyA = [&](int k0, int st) {
#pragma unroll
        for (int h = 0; h < 2; h++) {
            int m = ar + h * 64;
            size_t go = (size_t)(m0 + m) * K + k0 + ac;
            cpasync16(Ah + st * ASTAGE + m * APAD + ac, Wh + go);
            cpasync16(Al + st * ASTAGE + m * APAD + ac, Wl + go);
        }
    };
    auto ldgB = [&](int k0) {
#pragma unroll
        for (int h = 0; h < 2; h++) {
            int r = br + h * 16;
            const uint4* sp = (const uint4*)(Hsrc + (size_t)(k0 + r) * NPCOL + n0 + bc);
            e[h][0] = sp[0]; e[h][1] = sp[1];
        }
    };
    auto stsB = [&](int st) {
#pragma unroll
        for (int h = 0; h < 2; h++) {
            int r = br + h * 16;
            uint4 hv, lv;
            hv.x = __byte_perm(e[h][0].x, e[h][0].y, 0x5410); lv.x = __byte_perm(e[h][0].x, e[h][0].y, 0x7632);
            hv.y = __byte_perm(e[h][0].z, e[h][0].w, 0x5410); lv.y = __byte_perm(e[h][0].z, e[h][0].w, 0x7632);
            hv.z = __byte_perm(e[h][1].x, e[h][1].y, 0x5410); lv.z = __byte_perm(e[h][1].x, e[h][1].y, 0x7632);
            hv.w = __byte_perm(e[h][1].z, e[h][1].w, 0x5410); lv.w = __byte_perm(e[h][1].z, e[h][1].w, 0x7632);
            *(uint4*)(Bh + st * BSTAGE + r * BPAD + bc) = hv;
            *(uint4*)(Bl + st * BSTAGE + r * BPAD + bc) = lv;
        }
    };

    // prologue: fill stage 0
    copyA(0, 0);
    asm volatile("cp.async.commit_group;");
    ldgB(0);
    stsB(0);
    asm volatile("cp.async.wait_group 0;");
    __syncthreads();

    int s = 0;
    for (int k0 = 0; k0 < K; k0 += 32, s ^= 1) {
        bool has = (k0 + 32) < K;
        if (has) {
            copyA(k0 + 32, s ^ 1);
            asm volatile("cp.async.commit_group;");
            ldgB(k0 + 32);
        }
        const __nv_bfloat16* cAh = Ah + s * ASTAGE;
        const __nv_bfloat16* cAl = Al + s * ASTAGE;
        const __nv_bfloat16* cBh = Bh + s * BSTAGE;
        const __nv_bfloat16* cBl = Bl + s * BSTAGE;
#pragma unroll
        for (int kk = 0; kk < 2; kk++) {
            unsigned ah[4][4], al[4][4], bh[4][2], bl[4][2];
#pragma unroll
            for (int i = 0; i < 4; i++) {
                int off = (a_row + i * 16) * APAD + a_col + kk * 16;
                ldsm4(ah[i], sm_u32(cAh + off));
                ldsm4(al[i], sm_u32(cAl + off));
            }
#pragma unroll
            for (int jj = 0; jj < 2; jj++) {
                int off = (b_row + kk * 16) * BPAD + b_col + jj * 16;
                unsigned r4[4];
                ldsm4t(r4, sm_u32(cBh + off));
                bh[jj * 2][0] = r4[0]; bh[jj * 2][1] = r4[1];
                bh[jj * 2 + 1][0] = r4[2]; bh[jj * 2 + 1][1] = r4[3];
                ldsm4t(r4, sm_u32(cBl + off));
                bl[jj * 2][0] = r4[0]; bl[jj * 2][1] = r4[1];
                bl[jj * 2 + 1][0] = r4[2]; bl[jj * 2 + 1][1] = r4[3];
            }
#pragma unroll
            for (int i = 0; i < 4; i++)
#pragma unroll
                for (int j = 0; j < 4; j++) {
                    mma16816(acc[i][j], ah[i], bh[j]);
                    mma16816(acc[i][j], ah[i], bl[j]);
                    mma16816(acc[i][j], al[i], bh[j]);
                }
        }
        if (has) {
            stsB(s ^ 1);
            asm volatile("cp.async.wait_group 0;");
        }
        __syncthreads();
    }

    // epilogue: c1 broadcast (mode 0), store, fused BN stats
    int g = lane >> 2, tg = lane & 3;
    float* C = (mode == 0) ? g_h3 : g_h2;
    if (mode == 0) {
        int pt = (n0 + wn) >> 5;
#pragma unroll
        for (int i = 0; i < 4; i++) {
            int m = m0 + wm + i * 16 + g;
            float cv0 = g_c1[(size_t)m * NCENT + pt];
            float cv1 = g_c1[(size_t)(m + 8) * NCENT + pt];
#pragma unroll
            for (int j = 0; j < 4; j++) {
                acc[i][j][0] += cv0; acc[i][j][1] += cv0;
                acc[i][j][2] += cv1; acc[i][j][3] += cv1;
            }
        }
    }
#pragma unroll
    for (int i = 0; i < 4; i++) {
        int m = m0 + wm + i * 16 + g;
#pragma unroll
        for (int j = 0; j < 4; j++) {
            int n = n0 + wn + j * 8 + 2 * tg;
            *(float2*)(C + (size_t)m * NPCOL + n)       = make_float2(acc[i][j][0], acc[i][j][1]);
            *(float2*)(C + (size_t)(m + 8) * NPCOL + n) = make_float2(acc[i][j][2], acc[i][j][3]);
        }
    }
    // per-row partial sums -> shfl-reduce over tg -> smem atomics -> global atomics
#pragma unroll
    for (int i = 0; i < 4; i++) {
        float s1 = 0.f, q1 = 0.f, s2 = 0.f, q2 = 0.f;
#pragma unroll
        for (int j = 0; j < 4; j++) {
            s1 += acc[i][j][0] + acc[i][j][1];
            q1 += acc[i][j][0] * acc[i][j][0] + acc[i][j][1] * acc[i][j][1];
            s2 += acc[i][j][2] + acc[i][j][3];
            q2 += acc[i][j][2] * acc[i][j][2] + acc[i][j][3] * acc[i][j][3];
        }
#pragma unroll
        for (int o = 1; o <= 2; o <<= 1) {
            s1 += __shfl_xor_sync(0xFFFFFFFFu, s1, o);
            q1 += __shfl_xor_sync(0xFFFFFFFFu, q1, o);
            s2 += __shfl_xor_sync(0xFFFFFFFFu, s2, o);
            q2 += __shfl_xor_sync(0xFFFFFFFFu, q2, o);
        }
        if (tg == 0) {
            int r = wm + i * 16 + g;
            atomicAdd(&ssum[r], s1);     atomicAdd(&ssq[r], q1);
            atomicAdd(&ssum[r + 8], s2); atomicAdd(&ssq[r + 8], q2);
        }
    }
    __syncthreads();
    if (tid < 128) {
        atomicAdd(&g_sum[m0 + tid], ssum[tid]);
        atomicAdd(&g_sq[m0 + tid],  ssq[tid]);
    }
}

// ---------------- final: out_feat = max_k relu(bn4(h4)) ----------------
__global__ void final_kernel(float* __restrict__ out)
{
    int gid = blockIdx.x * 256 + threadIdx.x;
    int c = gid >> 12, pt = gid & 4095;
    float s = g_s4[c], t = g_t4[c];
    const float4* src = (const float4*)(g_h2 + (size_t)c * NPCOL + (size_t)pt * KNB);
    float m = 0.f;
#pragma unroll
    for (int i = 0; i < 8; i++) {
        float4 v = src[i];
        m = fmaxf(m, fmaxf(fmaxf(fmaf(v.x, s, t), fmaf(v.y, s, t)),
                           fmaxf(fmaf(v.z, s, t), fmaf(v.w, s, t))));
    }
    int b = pt >> 10, sIdx = pt & 1023;
    out[12288 + (size_t)((b << 8) + c) * 1024 + sIdx] = m;
}

// ---------------- launch ----------------
extern "C" void kernel_launch(void* const* d_in, const int* in_sizes, int n_in,
                              void* d_out, int out_size)
{
    const float* p   = (const float*)d_in[0];
    const float* f   = (const float*)d_in[1];
    const float* w1  = (const float*)d_in[2];
    const float* w2  = (const float*)d_in[3];
    const float* b2  = (const float*)d_in[4];
    const float* g2  = (const float*)d_in[5];
    const float* be2 = (const float*)d_in[6];
    const float* w3  = (const float*)d_in[7];
    const float* g3  = (const float*)d_in[8];
    const float* be3 = (const float*)d_in[9];
    const float* w4  = (const float*)d_in[10];
    const float* g4  = (const float*)d_in[11];
    const float* be4 = (const float*)d_in[12];
    float* out = (float*)d_out;

    cudaFuncSetAttribute(fps_kernel, cudaFuncAttributeMaxDynamicSharedMemorySize, 65536);
    cudaFuncSetAttribute(knn_kernel, cudaFuncAttributeMaxDynamicSharedMemorySize, 65536);
    cudaFuncSetAttribute(gemm_mma,  cudaFuncAttributeMaxDynamicSharedMemorySize, GSMEM);

    w12_kernel<<<1, 256>>>(w1, w2);
    wsplit_kernel<<<512, 256>>>(w3, w4);
    fps_kernel<<<BATCH, 1024, NPTS * 3 * sizeof(float)>>>(p, out);
    knn_kernel<<<BATCH * 128, 256, NPTS * 3 * sizeof(float)>>>(p);
    stage1_kernel<<<NCENT, 256>>>(p, f, b2);

    bnstats_kernel<<<256, 256>>>(0);
    bnfinal_kernel<<<1, 256>>>(0, 256, g2, be2);
    split0_kernel<<<NCENT, 256>>>();                        // split h2 + compute xm
    c1_kernel<<<dim3(NCENT / 128, 512 / 128), 256>>>(w3);

    zerostats_kernel<<<1, 512>>>();
    gemm_mma<<<dim3(512 / 128, NPCOL / 128), 256, GSMEM>>>(0);
    bnfinal_kernel<<<2, 256>>>(1, 512, g3, be3);
    split1_kernel<<<(512 * (NPCOL / 8)) / 256, 256>>>();    // split h3

    zerostats_kernel<<<1, 512>>>();
    gemm_mma<<<dim3(256 / 128, NPCOL / 128), 256, GSMEM>>>(1);
    bnfinal_kernel<<<1, 256>>>(2, 256, g4, be4);

    final_kernel<<<NCENT, 256>>>(out);
}